// round 8
// baseline (speedup 1.0000x reference)
#include <cuda_runtime.h>
#include <cstdint>

#define EPS 1e-5f
#define NBATCH 16
#define PER (4 * 1024 * 1024)               // elements per batch
#define PER4 (PER / 4)                      // float4s per batch = 1,048,576

#define THREADS 512
#define PROD_BLK 148                        // 1 producer / SM
#define CONS_BLK 296                        // 2 consumers / SM
#define NBLK (PROD_BLK + CONS_BLK)          // 444 co-resident (3/SM)

#define F4_PER_THREAD 8
#define ITEM_F4 (THREADS * F4_PER_THREAD)   // 4096 float4 = 64KB per item
#define ITEMS_PER_BATCH (PER4 / ITEM_F4)    // 256
#define LEAD 5                              // producer may lead consumers by <= LEAD batches

// Scratch (allocation-free -> __device__ globals, zero-initialized)
__device__ float        g_psum[NBATCH * ITEMS_PER_BATCH];
__device__ float        g_psumsq[NBATCH * ITEMS_PER_BATCH];
__device__ unsigned int g_pcnt[NBATCH * ITEMS_PER_BATCH];
__device__ float        g_mean[NBATCH];
__device__ float        g_inv[NBATCH];
__device__ unsigned int g_done[NBATCH];       // reduce items completed per batch
__device__ unsigned int g_flag[NBATCH];       // stats-ready flag per batch
__device__ unsigned int g_norm_done[NBATCH];  // normalize items completed per batch
__device__ unsigned int g_bar;                // monotonic grid-barrier counter (never reset)

// Monotonic-counter grid barrier (epilogue only): replay-safe, no reset needed.
__device__ __forceinline__ void grid_barrier() {
    __syncthreads();
    if (threadIdx.x == 0) {
        __threadfence();
        unsigned int old = atomicAdd(&g_bar, 1u);
        unsigned int target = (old / NBLK + 1u) * NBLK;
        volatile unsigned int* p = &g_bar;
        long long spins = 0;
        while (*p < target) {
            __nanosleep(64);
            if (++spins > 500000000LL) break;
        }
    }
    __syncthreads();
    __threadfence();
}

__global__ __launch_bounds__(THREADS, 3)
void fused_masked_normalize(const float4* __restrict__ x, float4* __restrict__ out) {
    const int t    = threadIdx.x;
    const int lane = t & 31;
    const int warp = t >> 5;

    __shared__ float        sh_s[THREADS / 32];
    __shared__ float        sh_ss[THREADS / 32];
    __shared__ unsigned int sh_c[THREADS / 32];
    __shared__ unsigned int sh_last;

    if (blockIdx.x < PROD_BLK) {
        // ================= PRODUCER: reduce + finalize =================
        const int pid = blockIdx.x;

        for (int b = 0; b < NBATCH; b++) {
            // Throttle: keep at most LEAD batches of x in flight in L2.
            if (b >= LEAD) {
                if (t == 0) {
                    volatile unsigned int* p = &g_norm_done[b - LEAD];
                    long long spins = 0;
                    while (*p < ITEMS_PER_BATCH) {
                        __nanosleep(128);
                        if (++spins > 500000000LL) break;   // bail: lose reuse, stay correct
                    }
                }
                __syncthreads();
            }

            const size_t bbase = (size_t)b * PER4;

            for (int item = pid; item < ITEMS_PER_BATCH; item += PROD_BLK) {
                const size_t base = bbase + (size_t)item * ITEM_F4 + t;

                float4 v[F4_PER_THREAD];
                #pragma unroll
                for (int k = 0; k < F4_PER_THREAD; k++)
                    v[k] = x[base + (size_t)k * THREADS];      // default: allocate in L2

                // Masked entries are exactly 0.0f -> sum/sumsq over all
                // elements equal the masked sums. Branch-free.
                float s = 0.f, ss = 0.f;
                unsigned int c = 0;
                #pragma unroll
                for (int k = 0; k < F4_PER_THREAD; k++) {
                    s  += v[k].x + v[k].y + v[k].z + v[k].w;
                    ss  = fmaf(v[k].x, v[k].x, ss);
                    ss  = fmaf(v[k].y, v[k].y, ss);
                    ss  = fmaf(v[k].z, v[k].z, ss);
                    ss  = fmaf(v[k].w, v[k].w, ss);
                    c  += (v[k].x != 0.f) + (v[k].y != 0.f) + (v[k].z != 0.f) + (v[k].w != 0.f);
                }

                // deterministic block reduce -> fixed slot
                #pragma unroll
                for (int off = 16; off > 0; off >>= 1) {
                    s  += __shfl_xor_sync(0xFFFFFFFFu, s,  off);
                    ss += __shfl_xor_sync(0xFFFFFFFFu, ss, off);
                    c  += __shfl_xor_sync(0xFFFFFFFFu, c,  off);
                }
                if (lane == 0) { sh_s[warp] = s; sh_ss[warp] = ss; sh_c[warp] = c; }
                __syncthreads();
                if (warp == 0) {
                    s  = (lane < THREADS / 32) ? sh_s[lane]  : 0.f;
                    ss = (lane < THREADS / 32) ? sh_ss[lane] : 0.f;
                    c  = (lane < THREADS / 32) ? sh_c[lane]  : 0u;
                    #pragma unroll
                    for (int off = 8; off > 0; off >>= 1) {
                        s  += __shfl_xor_sync(0xFFFFFFFFu, s,  off);
                        ss += __shfl_xor_sync(0xFFFFFFFFu, ss, off);
                        c  += __shfl_xor_sync(0xFFFFFFFFu, c,  off);
                    }
                    if (lane == 0) {
                        const int idx = b * ITEMS_PER_BATCH + item;
                        g_psum[idx] = s; g_psumsq[idx] = ss; g_pcnt[idx] = c;
                    }
                }
                __syncthreads();

                // last-item-of-batch detection -> inline finalize + flag release
                if (t == 0) {
                    __threadfence();
                    sh_last = (atomicAdd(&g_done[b], 1u) == ITEMS_PER_BATCH - 1u);
                }
                __syncthreads();
                if (sh_last) {
                    __threadfence();   // acquire all partials
                    double ds = 0.0, dss = 0.0;
                    unsigned long long dc = 0;
                    if (t < ITEMS_PER_BATCH) {
                        const int idx = b * ITEMS_PER_BATCH + t;
                        ds  = (double)g_psum[idx];
                        dss = (double)g_psumsq[idx];
                        dc  = g_pcnt[idx];
                    }
                    #pragma unroll
                    for (int off = 16; off > 0; off >>= 1) {
                        ds  += __shfl_xor_sync(0xFFFFFFFFu, ds,  off);
                        dss += __shfl_xor_sync(0xFFFFFFFFu, dss, off);
                        dc  += __shfl_xor_sync(0xFFFFFFFFu, dc,  off);
                    }
                    __shared__ double fs[THREADS / 32];
                    __shared__ double fss[THREADS / 32];
                    __shared__ unsigned long long fc[THREADS / 32];
                    if (lane == 0) { fs[warp] = ds; fss[warp] = dss; fc[warp] = dc; }
                    __syncthreads();
                    if (t == 0) {
                        double S = 0.0, SS = 0.0; unsigned long long C = 0;
                        #pragma unroll
                        for (int w = 0; w < (ITEMS_PER_BATCH + 31) / 32; w++) { S += fs[w]; SS += fss[w]; C += fc[w]; }
                        const double n    = (double)C;
                        const double mean = S / n;
                        const double var  = (SS - S * S / n) / (n - 1.0);  // m2 analytically 0
                        g_mean[b] = (float)mean;
                        g_inv[b]  = (float)(1.0 / (sqrt(var) + (double)EPS));
                        __threadfence();                      // release stats
                        atomicExch(&g_flag[b], 1u);
                    }
                    __syncthreads();
                }
            }
        }
    } else {
        // ================= CONSUMER: normalize =================
        const int cid = blockIdx.x - PROD_BLK;

        for (int b = 0; b < NBATCH; b++) {
            // wait for batch b stats
            if (t == 0) {
                volatile unsigned int* p = &g_flag[b];
                long long spins = 0;
                while (*p == 0u) {
                    __nanosleep(64);
                    if (++spins > 2000000000LL) break;
                }
            }
            __syncthreads();
            __threadfence();                                  // acquire stats + data
            const float mean = g_mean[b];
            const float inv  = g_inv[b];
            const size_t bbase = (size_t)b * PER4;

            for (int item = cid; item < ITEMS_PER_BATCH; item += CONS_BLK) {
                const size_t base = bbase + (size_t)item * ITEM_F4 + t;

                float4 v[F4_PER_THREAD];
                #pragma unroll
                for (int k = 0; k < F4_PER_THREAD; k++)
                    v[k] = __ldcs(&x[base + (size_t)k * THREADS]);  // L2-resident, dead after

                #pragma unroll
                for (int k = 0; k < F4_PER_THREAD; k++) {
                    float4 o;
                    o.x = (v[k].x != 0.f) ? (v[k].x - mean) * inv : 0.f;
                    o.y = (v[k].y != 0.f) ? (v[k].y - mean) * inv : 0.f;
                    o.z = (v[k].z != 0.f) ? (v[k].z - mean) * inv : 0.f;
                    o.w = (v[k].w != 0.f) ? (v[k].w - mean) * inv : 0.f;
                    __stcs(&out[base + (size_t)k * THREADS], o);    // don't evict resident x
                }
            }

            // signal normalize progress for producer throttle
            if (t == 0) {
                __threadfence();
                atomicAdd(&g_norm_done[b], (unsigned int)
                          ((ITEMS_PER_BATCH / CONS_BLK) +
                           (cid < (ITEMS_PER_BATCH % CONS_BLK) ? 1 : 0) == 0
                           ? 0u : 0u));  // placeholder, replaced below
            }
            // count items this block actually processed (deterministic)
            if (t == 0) {
                unsigned int mine = 0;
                for (int item = cid; item < ITEMS_PER_BATCH; item += CONS_BLK) mine++;
                if (mine) atomicAdd(&g_norm_done[b], mine);
                else      atomicAdd(&g_norm_done[b], 0u);
            }
            __syncthreads();
        }
        // blocks that processed zero items still contribute: ensure target reachable
        // (total adds across blocks == ITEMS_PER_BATCH exactly by construction)
    }

    // ---- epilogue: reset flags/counters for next graph replay ----
    grid_barrier();
    if (blockIdx.x == 0 && t < NBATCH) {
        g_done[t] = 0;
        g_flag[t] = 0;
        g_norm_done[t] = 0;
    }
}

extern "C" void kernel_launch(void* const* d_in, const int* in_sizes, int n_in,
                              void* d_out, int out_size) {
    const float4* x   = (const float4*)d_in[0];
    float4*       out = (float4*)d_out;
    fused_masked_normalize<<<NBLK, THREADS>>>(x, out);
}